// round 4
// baseline (speedup 1.0000x reference)
#include <cuda_runtime.h>

#define NN 50000
#define EE 800000
#define GG 512
#define DH 64
#define DE 16
#define NPB 112   // nodes per block in node_linear

// ---------------- scratch (device globals; no allocations allowed) ----------
__device__ __align__(16) float g_q[NN*DH];
__device__ __align__(16) float g_k[NN*DH];
__device__ __align__(16) float g_v[NN*DH];
__device__ __align__(16) float g_agg[NN*DH];   // skip connection (x@ws+bs)
__device__ __align__(16) float g_qwe[NN*DE];   // (we @ q) per node, 16 dims
__device__ __align__(16) float g_h[NN*DH];     // layer-1 output
__device__ __align__(16) float g_Wcat[DH*272]; // [64][q|k|v|skip|qwe(16)]
__device__ __align__(16) float g_Bcat[272];
__device__ __align__(16) float g_pooled[GG*DH];
// CSR over dst
__device__ int  g_deg[NN];
__device__ int  g_off[NN+1];
__device__ int  g_cur[NN];
__device__ __align__(16) int2 g_csr[EE];       // (src, edge_id) grouped by dst
// dtype flags (1 = int64, 0 = int32)
__device__ int  g_ei64;
__device__ int  g_b64;

// ---------------- helpers ---------------------------------------------------
__device__ __forceinline__ float leaky(float z){ return z >= 0.f ? z : 0.01f*z; }

__device__ __forceinline__ int getIdx(const void* p, long long i, int is64){
  if (is64) return (int)((const long long*)p)[i];
  return ((const int*)p)[i];
}
__device__ __forceinline__ int clampi(int v, int lo, int hi){
  return v < lo ? lo : (v > hi ? hi : v);
}

// ---------------- dtype detection -------------------------------------------
// int64 data has zero high-halves at odd 32-bit word positions; int32 data has
// live index values there. Sampling stays inside the int32-sized buffer so it
// is safe under either interpretation.
__global__ void detect_dtype(const void* ei, const void* batch){
  if (threadIdx.x != 0 || blockIdx.x != 0) return;
  const int* w = (const int*)ei;
  int all0 = 1;
  for (int i = 0; i < 64; i++){
    long long pos = 2LL*(i*12147 + 7) + 1;   // odd words, < 1.6M
    if (w[pos] != 0){ all0 = 0; break; }
  }
  g_ei64 = all0;
  const int* b = (const int*)batch;
  int all0b = 1;
  for (int i = 0; i < 32; i++){
    int pos = 49001 + 2*i;                   // odd words near the tail, < 50000
    if (b[pos] != 0){ all0b = 0; break; }
  }
  g_b64 = all0b;
}

// ---------------- CSR build -------------------------------------------------
__global__ void deg_zero(){
  int i = blockIdx.x*blockDim.x + threadIdx.x;
  if (i < NN) g_deg[i] = 0;
}
__global__ void deg_hist(const void* __restrict__ ei){
  int e = blockIdx.x*blockDim.x + threadIdx.x;
  if (e >= EE) return;
  int is64 = g_ei64;
  int d = clampi(getIdx(ei, (long long)EE + e, is64), 0, NN-1);
  atomicAdd(&g_deg[d], 1);
}
__global__ void __launch_bounds__(1024) scan_kernel(){
  __shared__ int warpsum[32];
  __shared__ int s_carry;
  int t = threadIdx.x;
  int lane = t & 31, w = t >> 5;
  if (t == 0) s_carry = 0;
  __syncthreads();
  for (int base = 0; base < NN; base += 1024){
    int v = (base + t < NN) ? g_deg[base + t] : 0;
    int x = v;
    #pragma unroll
    for (int o = 1; o < 32; o <<= 1){
      int y = __shfl_up_sync(0xffffffffu, x, o);
      if (lane >= o) x += y;
    }
    if (lane == 31) warpsum[w] = x;
    __syncthreads();
    if (w == 0){
      int s = warpsum[lane];
      #pragma unroll
      for (int o = 1; o < 32; o <<= 1){
        int y = __shfl_up_sync(0xffffffffu, s, o);
        if (lane >= o) s += y;
      }
      warpsum[lane] = s;
    }
    __syncthreads();
    int incl = x + (w > 0 ? warpsum[w-1] : 0);
    int ex = s_carry + incl - v;
    if (base + t < NN){ g_off[base + t] = ex; g_cur[base + t] = ex; }
    __syncthreads();
    if (t == 1023) s_carry += incl;
    __syncthreads();
  }
  if (t == 0) g_off[NN] = s_carry;
}
__global__ void csr_scatter(const void* __restrict__ ei){
  int e = blockIdx.x*blockDim.x + threadIdx.x;
  if (e >= EE) return;
  int is64 = g_ei64;
  int s = clampi(getIdx(ei, e, is64), 0, NN-1);
  int d = clampi(getIdx(ei, (long long)EE + e, is64), 0, NN-1);
  int p = atomicAdd(&g_cur[d], 1);
  if (p < EE) g_csr[p] = make_int2(s, e);
}

// ---------------- weight prep -----------------------------------------------
__global__ void build_wcat(const float* __restrict__ wq, const float* __restrict__ bq,
                           const float* __restrict__ wk, const float* __restrict__ bk,
                           const float* __restrict__ wv, const float* __restrict__ bv,
                           const float* __restrict__ we, const float* __restrict__ ws,
                           const float* __restrict__ bs){
  int idx = blockIdx.x*blockDim.x + threadIdx.x;
  if (idx < DH*272){
    int j = idx / 272, c = idx % 272;
    float val;
    if      (c < 64)  val = wq[j*64 + c];
    else if (c < 128) val = wk[j*64 + (c-64)];
    else if (c < 192) val = wv[j*64 + (c-128)];
    else if (c < 256) val = ws[j*64 + (c-192)];
    else { int d = c-256; float s = 0.f;
           for (int cc = 0; cc < 64; cc++) s += wq[j*64+cc]*we[d*64+cc];
           val = s; }
    g_Wcat[j*272 + c] = val;
  }
  if (idx < 272){
    int c = idx; float val;
    if      (c < 64)  val = bq[c];
    else if (c < 128) val = bk[c-64];
    else if (c < 192) val = bv[c-128];
    else if (c < 256) val = bs[c-192];
    else { int d = c-256; float s = 0.f;
           for (int cc = 0; cc < 64; cc++) s += bq[cc]*we[d*64+cc];
           val = s; }
    g_Bcat[c] = val;
  }
}

// ---------------- node GEMM: [NPB,64] x [64,272] -> q,k,v,skip,qwe ----------
__global__ void __launch_bounds__(256) node_linear(const float* __restrict__ xin, int useH){
  __shared__ __align__(16) float xs[NPB*65];
  __shared__ __align__(16) float sW[64*64];
  const float* src = useH ? g_h : xin;
  int t = threadIdx.x;
  int nbase = blockIdx.x * NPB;

  for (int idx = t; idx < NPB*64; idx += 256){
    int n = idx >> 6, kk = idx & 63;
    int gn = nbase + n;
    xs[n*65 + kk] = (gn < NN) ? src[gn*64 + kk] : 0.f;
  }
  __syncthreads();

  int cg = t & 15, ng = t >> 4;
  for (int ct = 0; ct < 5; ct++){
    int col0 = ct*64;
    int tw = (ct == 4) ? 16 : 64;
    for (int idx = t; idx < 64*tw; idx += 256){
      int kk = idx / tw, c = idx - kk*tw;
      sW[kk*64 + c] = g_Wcat[kk*272 + col0 + c];
    }
    __syncthreads();
    if (ct < 4 || cg < 4){
      float acc[7][4];
      #pragma unroll
      for (int i = 0; i < 7; i++)
        #pragma unroll
        for (int c = 0; c < 4; c++) acc[i][c] = 0.f;
      #pragma unroll 4
      for (int kk = 0; kk < 64; kk++){
        float4 w4 = *(const float4*)&sW[kk*64 + cg*4];
        #pragma unroll
        for (int i = 0; i < 7; i++){
          float xv = xs[(ng + i*16)*65 + kk];
          acc[i][0] = fmaf(xv, w4.x, acc[i][0]);
          acc[i][1] = fmaf(xv, w4.y, acc[i][1]);
          acc[i][2] = fmaf(xv, w4.z, acc[i][2]);
          acc[i][3] = fmaf(xv, w4.w, acc[i][3]);
        }
      }
      float* outp = (ct==0) ? g_q : (ct==1) ? g_k : (ct==2) ? g_v : (ct==3) ? g_agg : g_qwe;
      int ow = (ct == 4) ? 16 : 64;
      float b0 = g_Bcat[col0 + cg*4 + 0];
      float b1 = g_Bcat[col0 + cg*4 + 1];
      float b2 = g_Bcat[col0 + cg*4 + 2];
      float b3 = g_Bcat[col0 + cg*4 + 3];
      #pragma unroll
      for (int i = 0; i < 7; i++){
        int gn = nbase + ng + i*16;
        if (gn < NN){
          float4 r;
          r.x = acc[i][0] + b0; r.y = acc[i][1] + b1;
          r.z = acc[i][2] + b2; r.w = acc[i][3] + b3;
          *(float4*)&outp[gn*ow + cg*4] = r;
        }
      }
    }
    __syncthreads();
  }
}

// ---------------- fused attention: warp per dst node, online softmax --------
__global__ void __launch_bounds__(256) fused_attn(const float* __restrict__ ea,
                                                  const float* __restrict__ we,
                                                  float* __restrict__ emb_out,
                                                  int finalLayer){
  __shared__ __align__(16) float sWe[DE*DH];
  int t = threadIdx.x;
  for (int i = t; i < DE*DH; i += 256) sWe[i] = we[i];
  __syncthreads();

  int lane = t & 31, w = t >> 5;
  int n = blockIdx.x*8 + w;
  if (n >= NN) return;

  float2 q2 = *(const float2*)&g_q[n*64 + lane*2];
  float2 qe2 = make_float2(0.f, 0.f);
  if (lane < 8) qe2 = *(const float2*)&g_qwe[n*16 + lane*2];

  int s0 = g_off[n], s1 = g_off[n+1];

  float m = -1e30f, den = 0.f;
  float2 accv = make_float2(0.f, 0.f);
  float2 acce = make_float2(0.f, 0.f);

  for (int base = s0; base < s1; base += 32){
    int2 se = make_int2(0, 0);
    if (base + lane < s1) se = g_csr[base + lane];
    int cl = min(32, s1 - base);
    for (int j = 0; j < cl; j++){
      int srcn = __shfl_sync(0xffffffffu, se.x, j);
      int eid  = __shfl_sync(0xffffffffu, se.y, j);
      float2 kk = *(const float2*)&g_k[srcn*64 + lane*2];
      float2 vv = *(const float2*)&g_v[srcn*64 + lane*2];
      float2 ea2 = make_float2(0.f, 0.f);
      float part = q2.x*kk.x + q2.y*kk.y;
      if (lane < 8){
        ea2 = *(const float2*)&ea[(long long)eid*16 + lane*2];
        part += qe2.x*ea2.x + qe2.y*ea2.y;
      }
      #pragma unroll
      for (int o = 16; o; o >>= 1) part += __shfl_xor_sync(0xffffffffu, part, o);
      float s = part * 0.125f;
      float newm = fmaxf(m, s);
      float c = __expf(m - newm);
      float p = __expf(s - newm);
      den = den*c + p;
      accv.x = accv.x*c + p*vv.x;  accv.y = accv.y*c + p*vv.y;
      acce.x = acce.x*c + p*ea2.x; acce.y = acce.y*c + p*ea2.y;
      m = newm;
    }
  }

  float invden = (den > 0.f) ? (1.f / den) : 0.f;
  accv.x *= invden; accv.y *= invden;
  acce.x *= invden; acce.y *= invden;

  // edge-attr contribution through we: out += acce_full(16) @ we(16x64)
  float2 r = make_float2(0.f, 0.f);
  #pragma unroll
  for (int d8 = 0; d8 < 8; d8++){
    float ex = __shfl_sync(0xffffffffu, acce.x, d8);
    float ey = __shfl_sync(0xffffffffu, acce.y, d8);
    r.x += ex*sWe[(2*d8)*64 + lane*2]     + ey*sWe[(2*d8+1)*64 + lane*2];
    r.y += ex*sWe[(2*d8)*64 + lane*2 + 1] + ey*sWe[(2*d8+1)*64 + lane*2 + 1];
  }

  float2 sk = *(const float2*)&g_agg[n*64 + lane*2];
  float o0 = leaky(sk.x + accv.x + r.x);
  float o1 = leaky(sk.y + accv.y + r.y);
  float* dst = finalLayer ? emb_out : g_h;
  *(float2*)&dst[n*64 + lane*2] = make_float2(o0, o1);
}

// ---------------- pooling (batch is sorted) ---------------------------------
__device__ __forceinline__ int lbidx(const void* b, int val, int is64){
  int lo = 0, hi = NN;
  while (lo < hi){
    int mid = (lo + hi) >> 1;
    int v = is64 ? (int)((const long long*)b)[mid] : ((const int*)b)[mid];
    if (v < val) lo = mid + 1; else hi = mid;
  }
  return lo;
}
__global__ void __launch_bounds__(64) pool_kernel(const void* __restrict__ batch,
                                                  const float* __restrict__ embs){
  int g = blockIdx.x;
  int ch = threadIdx.x;
  int is64 = g_b64;
  int s = lbidx(batch, g, is64);
  int e = lbidx(batch, g + 1, is64);
  float sum = 0.f;
  for (int n = s; n < e; n++) sum += embs[n*64 + ch];
  g_pooled[g*64 + ch] = sum;
}

// ---------------- head ------------------------------------------------------
__global__ void __launch_bounds__(256) fc_kernel(const float* __restrict__ wfc1,
                                                 const float* __restrict__ bfc1,
                                                 const float* __restrict__ wfc2,
                                                 const float* __restrict__ bfc2,
                                                 float* __restrict__ out){
  __shared__ __align__(16) float sW1[64*64];
  __shared__ float sW2[64];
  __shared__ float sB1[64];
  int t = threadIdx.x;
  for (int i = t; i < 4096; i += 256) sW1[i] = wfc1[i];
  if (t < 64){ sW2[t] = wfc2[t]; sB1[t] = bfc1[t]; }
  __syncthreads();
  int lane = t & 31, w = t >> 5;
  int g = blockIdx.x*8 + w;
  if (g >= GG) return;
  float p0 = g_pooled[g*64 + lane], p1 = g_pooled[g*64 + 32 + lane];
  float ss = p0*p0 + p1*p1;
  #pragma unroll
  for (int o = 16; o; o >>= 1) ss += __shfl_xor_sync(0xffffffffu, ss, o);
  float inv = 1.f / fmaxf(sqrtf(ss), 1e-12f);
  float h0 = p0*inv, h1 = p1*inv;
  float acc0 = sB1[lane], acc1 = sB1[32 + lane];
  #pragma unroll
  for (int j = 0; j < 64; j++){
    float hj = (j < 32) ? __shfl_sync(0xffffffffu, h0, j)
                        : __shfl_sync(0xffffffffu, h1, j-32);
    acc0 += hj * sW1[j*64 + lane];
    acc1 += hj * sW1[j*64 + 32 + lane];
  }
  acc0 = leaky(acc0); acc1 = leaky(acc1);
  float r = acc0*sW2[lane] + acc1*sW2[32 + lane];
  #pragma unroll
  for (int o = 16; o; o >>= 1) r += __shfl_xor_sync(0xffffffffu, r, o);
  if (lane == 0) out[g] = r + bfc2[0];
}

// ---------------- launch ----------------------------------------------------
extern "C" void kernel_launch(void* const* d_in, const int* in_sizes, int n_in,
                              void* d_out, int out_size){
  // Locate the 4 large inputs by unique element counts (robust to ordering).
  int ix = -1, ie = -1, iea = -1, ib = -1;
  for (int i = 0; i < n_in; i++){
    if      (in_sizes[i] == NN*DH)   ix  = i;   // 3,200,000
    else if (in_sizes[i] == 2*EE)    ie  = i;   // 1,600,000
    else if (in_sizes[i] == EE*DE)   iea = i;   // 12,800,000
    else if (in_sizes[i] == NN)      ib  = i;   // 50,000
  }
  if (ix < 0) ix = 0; if (ie < 0) ie = 1; if (iea < 0) iea = 2; if (ib < 0) ib = 3;

  const float* x     = (const float*)d_in[ix];
  const void*  ei    = d_in[ie];
  const float* ea    = (const float*)d_in[iea];
  const void*  batch = d_in[ib];

  // Remaining inputs in order = weight list in reference dict order.
  const float* wp[22]; int nw = 0;
  for (int i = 0; i < n_in && nw < 22; i++){
    if (i == ix || i == ie || i == iea || i == ib) continue;
    wp[nw++] = (const float*)d_in[i];
  }
  const float *wq1=wp[0],  *bq1=wp[1],  *wk1=wp[2],  *bk1=wp[3];
  const float *wv1=wp[4],  *bv1=wp[5],  *we1=wp[6],  *ws1=wp[7],  *bs1=wp[8];
  const float *wq2=wp[9],  *bq2=wp[10], *wk2=wp[11], *bk2=wp[12];
  const float *wv2=wp[13], *bv2=wp[14], *we2=wp[15], *ws2=wp[16], *bs2=wp[17];
  const float *wfc1=wp[18], *bfc1=wp[19], *wfc2=wp[20], *bfc2=wp[21];

  float* out  = (float*)d_out;
  float* embs = out + GG;   // tuple order: (out[512,1], atom_embs[50000,64])

  const int GRID_NL = (NN + NPB - 1) / NPB;   // 447
  const int GRID_E  = EE / 256;               // 3125 exact
  const int GRID_N  = (NN + 255) / 256;       // 196
  const int GRID_FA = (NN + 7) / 8;           // 6250

  // dtype detection + CSR build (shared by both layers)
  detect_dtype<<<1, 32>>>(ei, batch);
  deg_zero<<<GRID_N, 256>>>();
  deg_hist<<<GRID_E, 256>>>(ei);
  scan_kernel<<<1, 1024>>>();
  csr_scatter<<<GRID_E, 256>>>(ei);

  // layer 1
  build_wcat<<<68, 256>>>(wq1, bq1, wk1, bk1, wv1, bv1, we1, ws1, bs1);
  node_linear<<<GRID_NL, 256>>>(x, 0);
  fused_attn<<<GRID_FA, 256>>>(ea, we1, nullptr, 0);

  // layer 2
  build_wcat<<<68, 256>>>(wq2, bq2, wk2, bk2, wv2, bv2, we2, ws2, bs2);
  node_linear<<<GRID_NL, 256>>>(x, 1);
  fused_attn<<<GRID_FA, 256>>>(ea, we2, embs, 1);

  // pooling + head
  pool_kernel<<<GG, 64>>>(batch, embs);
  fc_kernel<<<(GG + 7) / 8, 256>>>(wfc1, bfc1, wfc2, bfc2, out);
}

// round 5
// speedup vs baseline: 1.1658x; 1.1658x over previous
#include <cuda_runtime.h>

#define NN 50000
#define EE 800000
#define GG 512
#define DH 64
#define DE 16
#define NPB 112     // nodes per block in node_linear
#define SCB 49      // scan blocks (49*1024 >= NN)
#define FULLM 0xffffffffu

// ---------------- scratch (device globals; no allocations allowed) ----------
__device__ __align__(16) float g_q[NN*DH];
__device__ __align__(16) float g_k[NN*DH];
__device__ __align__(16) float g_v[NN*DH];
__device__ __align__(16) float g_agg[NN*DH];   // skip connection (x@ws+bs)
__device__ __align__(16) float g_qwe[NN*DE];   // (we @ q) per node, 16 dims
__device__ __align__(16) float g_h[NN*DH];     // layer-1 output
__device__ __align__(16) float g_Wcat[DH*272]; // [64][q|k|v|skip|qwe(16)]
__device__ __align__(16) float g_Bcat[272];
__device__ __align__(16) float g_pooled[GG*DH];
// CSR over dst
__device__ int  g_deg[NN];
__device__ int  g_off[NN+1];
__device__ int  g_cur[NN];
__device__ int  g_part[SCB];
__device__ __align__(16) int2 g_csr[EE];       // (src, edge_id) grouped by dst
// dtype flags (1 = int64, 0 = int32)
__device__ int  g_ei64;
__device__ int  g_b64;

// ---------------- helpers ---------------------------------------------------
__device__ __forceinline__ float leaky(float z){ return z >= 0.f ? z : 0.01f*z; }

__device__ __forceinline__ int getIdx(const void* p, long long i, int is64){
  if (is64) return (int)((const long long*)p)[i];
  return ((const int*)p)[i];
}
__device__ __forceinline__ int clampi(int v, int lo, int hi){
  return v < lo ? lo : (v > hi ? hi : v);
}

__device__ __forceinline__ unsigned long long pk(float a, float b){
  unsigned long long r;
  asm("mov.b64 %0, {%1, %2};" : "=l"(r) : "f"(a), "f"(b));
  return r;
}
__device__ __forceinline__ void upk(unsigned long long r, float& a, float& b){
  asm("mov.b64 {%0, %1}, %2;" : "=f"(a), "=f"(b) : "l"(r));
}
__device__ __forceinline__ void ffma2(unsigned long long& d, unsigned long long a, unsigned long long b){
  asm("fma.rn.f32x2 %0, %1, %2, %0;" : "+l"(d) : "l"(a), "l"(b));
}

// ---------------- dtype detection -------------------------------------------
__global__ void detect_dtype(const void* ei, const void* batch){
  if (threadIdx.x != 0 || blockIdx.x != 0) return;
  const int* w = (const int*)ei;
  int all0 = 1;
  for (int i = 0; i < 64; i++){
    long long pos = 2LL*(i*12147 + 7) + 1;   // odd words, < 1.6M
    if (w[pos] != 0){ all0 = 0; break; }
  }
  g_ei64 = all0;
  const int* b = (const int*)batch;
  int all0b = 1;
  for (int i = 0; i < 32; i++){
    int pos = 49001 + 2*i;
    if (b[pos] != 0){ all0b = 0; break; }
  }
  g_b64 = all0b;
}

// ---------------- CSR build -------------------------------------------------
__global__ void deg_zero(){
  int i = blockIdx.x*blockDim.x + threadIdx.x;
  if (i < NN) g_deg[i] = 0;
}
__global__ void deg_hist(const void* __restrict__ ei){
  int e = blockIdx.x*blockDim.x + threadIdx.x;
  if (e >= EE) return;
  int is64 = g_ei64;
  int d = clampi(getIdx(ei, (long long)EE + e, is64), 0, NN-1);
  atomicAdd(&g_deg[d], 1);
}

// hierarchical exclusive scan of g_deg -> g_off / g_cur
__global__ void __launch_bounds__(1024) scan_part(){
  int t = threadIdx.x;
  int i = blockIdx.x*1024 + t;
  int v = (i < NN) ? g_deg[i] : 0;
  int lane = t & 31, w = t >> 5;
  int s = v;
  #pragma unroll
  for (int o = 16; o; o >>= 1) s += __shfl_xor_sync(FULLM, s, o);
  __shared__ int ws[32];
  if (lane == 0) ws[w] = s;
  __syncthreads();
  if (w == 0){
    int x = ws[lane];
    #pragma unroll
    for (int o = 16; o; o >>= 1) x += __shfl_xor_sync(FULLM, x, o);
    if (lane == 0) g_part[blockIdx.x] = x;
  }
}
__global__ void __launch_bounds__(64) scan_base(){
  int t = threadIdx.x, lane = t & 31, w = t >> 5;
  int v = (t < SCB) ? g_part[t] : 0;
  int x = v;
  #pragma unroll
  for (int o = 1; o < 32; o <<= 1){
    int y = __shfl_up_sync(FULLM, x, o);
    if (lane >= o) x += y;
  }
  __shared__ int w0;
  if (w == 0 && lane == 31) w0 = x;
  __syncthreads();
  int incl = x + (w ? w0 : 0);
  if (t < SCB) g_part[t] = incl - v;      // exclusive block base
  if (t == SCB-1) g_off[NN] = incl;       // total
}
__global__ void __launch_bounds__(1024) scan_final(){
  int t = threadIdx.x;
  int i = blockIdx.x*1024 + t;
  int v = (i < NN) ? g_deg[i] : 0;
  int lane = t & 31, w = t >> 5;
  int x = v;
  #pragma unroll
  for (int o = 1; o < 32; o <<= 1){
    int y = __shfl_up_sync(FULLM, x, o);
    if (lane >= o) x += y;
  }
  __shared__ int ws[32];
  if (lane == 31) ws[w] = x;
  __syncthreads();
  if (w == 0){
    int s = ws[lane];
    #pragma unroll
    for (int o = 1; o < 32; o <<= 1){
      int y = __shfl_up_sync(FULLM, s, o);
      if (lane >= o) s += y;
    }
    ws[lane] = s;
  }
  __syncthreads();
  int incl = x + (w ? ws[w-1] : 0);
  int ex = g_part[blockIdx.x] + incl - v;
  if (i < NN){ g_off[i] = ex; g_cur[i] = ex; }
}
__global__ void csr_scatter(const void* __restrict__ ei){
  int e = blockIdx.x*blockDim.x + threadIdx.x;
  if (e >= EE) return;
  int is64 = g_ei64;
  int s = clampi(getIdx(ei, e, is64), 0, NN-1);
  int d = clampi(getIdx(ei, (long long)EE + e, is64), 0, NN-1);
  int p = atomicAdd(&g_cur[d], 1);
  if (p < EE) g_csr[p] = make_int2(s, e);
}

// ---------------- weight prep -----------------------------------------------
__global__ void build_wcat(const float* __restrict__ wq, const float* __restrict__ bq,
                           const float* __restrict__ wk, const float* __restrict__ bk,
                           const float* __restrict__ wv, const float* __restrict__ bv,
                           const float* __restrict__ we, const float* __restrict__ ws,
                           const float* __restrict__ bs){
  int idx = blockIdx.x*blockDim.x + threadIdx.x;
  if (idx < DH*272){
    int j = idx / 272, c = idx % 272;
    float val;
    if      (c < 64)  val = wq[j*64 + c];
    else if (c < 128) val = wk[j*64 + (c-64)];
    else if (c < 192) val = wv[j*64 + (c-128)];
    else if (c < 256) val = ws[j*64 + (c-192)];
    else { int d = c-256; float s = 0.f;
           for (int cc = 0; cc < 64; cc++) s += wq[j*64+cc]*we[d*64+cc];
           val = s; }
    g_Wcat[j*272 + c] = val;
  }
  if (idx < 272){
    int c = idx; float val;
    if      (c < 64)  val = bq[c];
    else if (c < 128) val = bk[c-64];
    else if (c < 192) val = bv[c-128];
    else if (c < 256) val = bs[c-192];
    else { int d = c-256; float s = 0.f;
           for (int cc = 0; cc < 64; cc++) s += bq[cc]*we[d*64+cc];
           val = s; }
    g_Bcat[c] = val;
  }
}

// ---------------- node GEMM (FFMA2): [NPB,64] x [64,272] --------------------
__global__ void __launch_bounds__(256) node_linear(const float* __restrict__ xin, int useH){
  __shared__ __align__(16) float xs[NPB*65];
  __shared__ __align__(16) float sW[64*64];
  const float* src = useH ? g_h : xin;
  int t = threadIdx.x;
  int nbase = blockIdx.x * NPB;

  for (int idx = t; idx < NPB*64; idx += 256){
    int n = idx >> 6, kk = idx & 63;
    int gn = nbase + n;
    xs[n*65 + kk] = (gn < NN) ? src[gn*64 + kk] : 0.f;
  }
  __syncthreads();

  int cg = t & 15, ng = t >> 4;
  for (int ct = 0; ct < 5; ct++){
    int col0 = ct*64;
    int tw = (ct == 4) ? 16 : 64;
    for (int idx = t; idx < 64*tw; idx += 256){
      int kk = idx / tw, c = idx - kk*tw;
      sW[kk*64 + c] = g_Wcat[kk*272 + col0 + c];
    }
    __syncthreads();
    if (ct < 4 || cg < 4){
      unsigned long long acclo[7], acchi[7];
      #pragma unroll
      for (int i = 0; i < 7; i++){ acclo[i] = 0ull; acchi[i] = 0ull; }
      #pragma unroll 8
      for (int kk = 0; kk < 64; kk++){
        float4 w4 = *(const float4*)&sW[kk*64 + cg*4];
        unsigned long long wlo = pk(w4.x, w4.y);
        unsigned long long whi = pk(w4.z, w4.w);
        #pragma unroll
        for (int i = 0; i < 7; i++){
          float xv = xs[(ng + i*16)*65 + kk];
          unsigned long long xx = pk(xv, xv);
          ffma2(acclo[i], wlo, xx);
          ffma2(acchi[i], whi, xx);
        }
      }
      float* outp = (ct==0) ? g_q : (ct==1) ? g_k : (ct==2) ? g_v : (ct==3) ? g_agg : g_qwe;
      int ow = (ct == 4) ? 16 : 64;
      float b0 = g_Bcat[col0 + cg*4 + 0];
      float b1 = g_Bcat[col0 + cg*4 + 1];
      float b2 = g_Bcat[col0 + cg*4 + 2];
      float b3 = g_Bcat[col0 + cg*4 + 3];
      #pragma unroll
      for (int i = 0; i < 7; i++){
        int gn = nbase + ng + i*16;
        if (gn < NN){
          float l0, l1, h0, h1;
          upk(acclo[i], l0, l1); upk(acchi[i], h0, h1);
          float4 r; r.x = l0 + b0; r.y = l1 + b1; r.z = h0 + b2; r.w = h1 + b3;
          *(float4*)&outp[gn*ow + cg*4] = r;
        }
      }
    }
    __syncthreads();
  }
}

// ---------------- fused attention: warp/node, 2 edges per iteration ---------
__global__ void __launch_bounds__(256) fused_attn(const float* __restrict__ ea,
                                                  const float* __restrict__ we,
                                                  float* __restrict__ emb_out,
                                                  int finalLayer){
  __shared__ __align__(16) float sWe[DE*DH];
  int t = threadIdx.x;
  for (int i = t; i < DE*DH; i += 256) sWe[i] = we[i];
  __syncthreads();

  int lane = t & 31, w = t >> 5;
  int n = blockIdx.x*8 + w;
  if (n >= NN) return;

  int hl = lane & 15;        // lane within half-warp
  int half = lane >> 4;      // which edge of the pair

  float4 q4 = *(const float4*)&g_q[n*64 + hl*4];
  float4 qe4 = make_float4(0.f,0.f,0.f,0.f);
  if (hl < 4) qe4 = *(const float4*)&g_qwe[n*16 + hl*4];

  int s0 = g_off[n], s1 = g_off[n+1];

  float m = -1e30f, den = 0.f;
  float4 accv = make_float4(0.f,0.f,0.f,0.f);
  float4 acce = make_float4(0.f,0.f,0.f,0.f);

  for (int base = s0; base < s1; base += 32){
    int2 se = (base + lane < s1) ? g_csr[base + lane] : make_int2(0, 0);
    int cnt = min(32, s1 - base);
    int npair = (cnt + 1) >> 1;
    for (int j = 0; j < npair; j++){
      int sl = 2*j + half;
      int srcn = __shfl_sync(FULLM, se.x, sl);
      int eid  = __shfl_sync(FULLM, se.y, sl);
      bool valid = (sl < cnt);
      float4 k4 = *(const float4*)&g_k[srcn*64 + hl*4];
      float4 v4 = *(const float4*)&g_v[srcn*64 + hl*4];
      float part = q4.x*k4.x + q4.y*k4.y + q4.z*k4.z + q4.w*k4.w;
      float4 ea4 = make_float4(0.f,0.f,0.f,0.f);
      if (hl < 4){
        ea4 = *(const float4*)&ea[(long long)eid*16 + hl*4];
        part += qe4.x*ea4.x + qe4.y*ea4.y + qe4.z*ea4.z + qe4.w*ea4.w;
      }
      part += __shfl_xor_sync(FULLM, part, 8);
      part += __shfl_xor_sync(FULLM, part, 4);
      part += __shfl_xor_sync(FULLM, part, 2);
      part += __shfl_xor_sync(FULLM, part, 1);
      if (valid){
        float s = part * 0.125f;
        float newm = fmaxf(m, s);
        float c = __expf(m - newm);
        float p = __expf(s - newm);
        den = den*c + p;
        accv.x = accv.x*c + p*v4.x;  accv.y = accv.y*c + p*v4.y;
        accv.z = accv.z*c + p*v4.z;  accv.w = accv.w*c + p*v4.w;
        acce.x = acce.x*c + p*ea4.x; acce.y = acce.y*c + p*ea4.y;
        acce.z = acce.z*c + p*ea4.z; acce.w = acce.w*c + p*ea4.w;
        m = newm;
      }
    }
  }

  // merge the two half-warp softmax states
  float m2   = __shfl_xor_sync(FULLM, m, 16);
  float den2 = __shfl_xor_sync(FULLM, den, 16);
  float4 av2, ae2;
  av2.x = __shfl_xor_sync(FULLM, accv.x, 16); av2.y = __shfl_xor_sync(FULLM, accv.y, 16);
  av2.z = __shfl_xor_sync(FULLM, accv.z, 16); av2.w = __shfl_xor_sync(FULLM, accv.w, 16);
  ae2.x = __shfl_xor_sync(FULLM, acce.x, 16); ae2.y = __shfl_xor_sync(FULLM, acce.y, 16);
  ae2.z = __shfl_xor_sync(FULLM, acce.z, 16); ae2.w = __shfl_xor_sync(FULLM, acce.w, 16);
  float M = fmaxf(m, m2);
  float c1 = __expf(m - M), c2 = __expf(m2 - M);
  den = den*c1 + den2*c2;
  accv.x = accv.x*c1 + av2.x*c2; accv.y = accv.y*c1 + av2.y*c2;
  accv.z = accv.z*c1 + av2.z*c2; accv.w = accv.w*c1 + av2.w*c2;
  acce.x = acce.x*c1 + ae2.x*c2; acce.y = acce.y*c1 + ae2.y*c2;
  acce.z = acce.z*c1 + ae2.z*c2; acce.w = acce.w*c1 + ae2.w*c2;

  float invden = (den > 0.f) ? (1.f / den) : 0.f;
  accv.x *= invden; accv.y *= invden; accv.z *= invden; accv.w *= invden;
  acce.x *= invden; acce.y *= invden; acce.z *= invden; acce.w *= invden;

  // edge-attr contribution through we: out += acce(16) @ we(16x64)
  float4 r = make_float4(0.f,0.f,0.f,0.f);
  #pragma unroll
  for (int d = 0; d < 16; d++){
    int srcl = (d >> 2) | (half << 4);   // read from own half's copy (identical)
    float ev;
    switch (d & 3){
      case 0: ev = __shfl_sync(FULLM, acce.x, srcl); break;
      case 1: ev = __shfl_sync(FULLM, acce.y, srcl); break;
      case 2: ev = __shfl_sync(FULLM, acce.z, srcl); break;
      default: ev = __shfl_sync(FULLM, acce.w, srcl); break;
    }
    r.x += ev*sWe[d*64 + hl*4 + 0];
    r.y += ev*sWe[d*64 + hl*4 + 1];
    r.z += ev*sWe[d*64 + hl*4 + 2];
    r.w += ev*sWe[d*64 + hl*4 + 3];
  }

  if (half == 0){
    float4 sk = *(const float4*)&g_agg[n*64 + hl*4];
    float4 o;
    o.x = leaky(sk.x + accv.x + r.x);
    o.y = leaky(sk.y + accv.y + r.y);
    o.z = leaky(sk.z + accv.z + r.z);
    o.w = leaky(sk.w + accv.w + r.w);
    float* dst = finalLayer ? emb_out : g_h;
    *(float4*)&dst[n*64 + hl*4] = o;
  }
}

// ---------------- pooling (batch is sorted) ---------------------------------
__device__ __forceinline__ int lbidx(const void* b, int val, int is64){
  int lo = 0, hi = NN;
  while (lo < hi){
    int mid = (lo + hi) >> 1;
    int v = is64 ? (int)((const long long*)b)[mid] : ((const int*)b)[mid];
    if (v < val) lo = mid + 1; else hi = mid;
  }
  return lo;
}
__global__ void __launch_bounds__(256) pool_kernel(const void* __restrict__ batch,
                                                   const float* __restrict__ embs){
  __shared__ float sp[4][64];
  int g = blockIdx.x;
  int t = threadIdx.x;
  int ch = t & 63, r = t >> 6;
  int is64 = g_b64;
  int s = lbidx(batch, g, is64);
  int e = lbidx(batch, g + 1, is64);
  float sum = 0.f;
  for (int n = s + r; n < e; n += 4) sum += embs[n*64 + ch];
  sp[r][ch] = sum;
  __syncthreads();
  if (r == 0)
    g_pooled[g*64 + ch] = sp[0][ch] + sp[1][ch] + sp[2][ch] + sp[3][ch];
}

// ---------------- head ------------------------------------------------------
__global__ void __launch_bounds__(256) fc_kernel(const float* __restrict__ wfc1,
                                                 const float* __restrict__ bfc1,
                                                 const float* __restrict__ wfc2,
                                                 const float* __restrict__ bfc2,
                                                 float* __restrict__ out){
  __shared__ __align__(16) float sW1[64*64];
  __shared__ float sW2[64];
  __shared__ float sB1[64];
  int t = threadIdx.x;
  for (int i = t; i < 4096; i += 256) sW1[i] = wfc1[i];
  if (t < 64){ sW2[t] = wfc2[t]; sB1[t] = bfc1[t]; }
  __syncthreads();
  int lane = t & 31, w = t >> 5;
  int g = blockIdx.x*8 + w;
  if (g >= GG) return;
  float p0 = g_pooled[g*64 + lane], p1 = g_pooled[g*64 + 32 + lane];
  float ss = p0*p0 + p1*p1;
  #pragma unroll
  for (int o = 16; o; o >>= 1) ss += __shfl_xor_sync(FULLM, ss, o);
  float inv = 1.f / fmaxf(sqrtf(ss), 1e-12f);
  float h0 = p0*inv, h1 = p1*inv;
  float acc0 = sB1[lane], acc1 = sB1[32 + lane];
  #pragma unroll
  for (int j = 0; j < 64; j++){
    float hj = (j < 32) ? __shfl_sync(FULLM, h0, j)
                        : __shfl_sync(FULLM, h1, j-32);
    acc0 += hj * sW1[j*64 + lane];
    acc1 += hj * sW1[j*64 + 32 + lane];
  }
  acc0 = leaky(acc0); acc1 = leaky(acc1);
  float r = acc0*sW2[lane] + acc1*sW2[32 + lane];
  #pragma unroll
  for (int o = 16; o; o >>= 1) r += __shfl_xor_sync(FULLM, r, o);
  if (lane == 0) out[g] = r + bfc2[0];
}

// ---------------- launch ----------------------------------------------------
extern "C" void kernel_launch(void* const* d_in, const int* in_sizes, int n_in,
                              void* d_out, int out_size){
  int ix = -1, ie = -1, iea = -1, ib = -1;
  for (int i = 0; i < n_in; i++){
    if      (in_sizes[i] == NN*DH)   ix  = i;
    else if (in_sizes[i] == 2*EE)    ie  = i;
    else if (in_sizes[i] == EE*DE)   iea = i;
    else if (in_sizes[i] == NN)      ib  = i;
  }
  if (ix < 0) ix = 0; if (ie < 0) ie = 1; if (iea < 0) iea = 2; if (ib < 0) ib = 3;

  const float* x     = (const float*)d_in[ix];
  const void*  ei    = d_in[ie];
  const float* ea    = (const float*)d_in[iea];
  const void*  batch = d_in[ib];

  const float* wp[22]; int nw = 0;
  for (int i = 0; i < n_in && nw < 22; i++){
    if (i == ix || i == ie || i == iea || i == ib) continue;
    wp[nw++] = (const float*)d_in[i];
  }
  const float *wq1=wp[0],  *bq1=wp[1],  *wk1=wp[2],  *bk1=wp[3];
  const float *wv1=wp[4],  *bv1=wp[5],  *we1=wp[6],  *ws1=wp[7],  *bs1=wp[8];
  const float *wq2=wp[9],  *bq2=wp[10], *wk2=wp[11], *bk2=wp[12];
  const float *wv2=wp[13], *bv2=wp[14], *we2=wp[15], *ws2=wp[16], *bs2=wp[17];
  const float *wfc1=wp[18], *bfc1=wp[19], *wfc2=wp[20], *bfc2=wp[21];

  float* out  = (float*)d_out;
  float* embs = out + GG;   // tuple order: (out[512,1], atom_embs[50000,64])

  const int GRID_NL = (NN + NPB - 1) / NPB;   // 447
  const int GRID_E  = EE / 256;               // 3125 exact
  const int GRID_N  = (NN + 255) / 256;       // 196
  const int GRID_FA = (NN + 7) / 8;           // 6250

  // dtype detection + CSR build (shared by both layers)
  detect_dtype<<<1, 32>>>(ei, batch);
  deg_zero<<<GRID_N, 256>>>();
  deg_hist<<<GRID_E, 256>>>(ei);
  scan_part<<<SCB, 1024>>>();
  scan_base<<<1, 64>>>();
  scan_final<<<SCB, 1024>>>();
  csr_scatter<<<GRID_E, 256>>>(ei);

  // layer 1
  build_wcat<<<68, 256>>>(wq1, bq1, wk1, bk1, wv1, bv1, we1, ws1, bs1);
  node_linear<<<GRID_NL, 256>>>(x, 0);
  fused_attn<<<GRID_FA, 256>>>(ea, we1, nullptr, 0);

  // layer 2
  build_wcat<<<68, 256>>>(wq2, bq2, wk2, bk2, wv2, bv2, we2, ws2, bs2);
  node_linear<<<GRID_NL, 256>>>(x, 1);
  fused_attn<<<GRID_FA, 256>>>(ea, we2, embs, 1);

  // pooling + head
  pool_kernel<<<GG, 256>>>(batch, embs);
  fc_kernel<<<(GG + 7) / 8, 256>>>(wfc1, bfc1, wfc2, bfc2, out);
}

// round 7
// speedup vs baseline: 1.1820x; 1.0139x over previous
#include <cuda_runtime.h>

#define NN 50000
#define EE 800000
#define GG 512
#define DH 64
#define DE 16
#define NPB 112     // nodes per block in node_linear
#define SCB 49      // scan blocks (49*1024 >= NN)
#define FULLM 0xffffffffu

// ---------------- scratch (device globals; no allocations allowed) ----------
__device__ __align__(16) float g_q[NN*DH];
__device__ __align__(16) float g_k[NN*DH];
__device__ __align__(16) float g_v[NN*DH];
__device__ __align__(16) float g_agg[NN*DH];   // skip connection (x@ws+bs)
__device__ __align__(16) float g_qwe[NN*DE];   // (we @ q) per node, 16 dims
__device__ __align__(16) float g_h[NN*DH];     // layer-1 output
__device__ __align__(16) float g_Wcat[2][DH*272]; // [64][q|k|v|skip|qwe(16)]
__device__ __align__(16) float g_Bcat[2][272];
__device__ __align__(16) float g_pooled[GG*DH];
// CSR over dst
__device__ int  g_deg[NN];
__device__ int  g_off[NN+1];
__device__ int  g_cur[NN];
__device__ int  g_part[SCB];
__device__ __align__(16) int2 g_csr[EE];       // (src, edge_id) grouped by dst
// dtype flags (1 = int64, 0 = int32)
__device__ int  g_ei64;
__device__ int  g_b64;

// ---------------- helpers ---------------------------------------------------
__device__ __forceinline__ float leaky(float z){ return z >= 0.f ? z : 0.01f*z; }

__device__ __forceinline__ int getIdx(const void* p, long long i, int is64){
  if (is64) return (int)((const long long*)p)[i];
  return ((const int*)p)[i];
}
__device__ __forceinline__ int clampi(int v, int lo, int hi){
  return v < lo ? lo : (v > hi ? hi : v);
}

__device__ __forceinline__ unsigned long long pk(float a, float b){
  unsigned long long r;
  asm("mov.b64 %0, {%1, %2};" : "=l"(r) : "f"(a), "f"(b));
  return r;
}
__device__ __forceinline__ void upk(unsigned long long r, float& a, float& b){
  asm("mov.b64 {%0, %1}, %2;" : "=f"(a), "=f"(b) : "l"(r));
}
__device__ __forceinline__ void ffma2(unsigned long long& d, unsigned long long a, unsigned long long b){
  asm("fma.rn.f32x2 %0, %1, %2, %0;" : "+l"(d) : "l"(a), "l"(b));
}

// ---------------- dtype detection -------------------------------------------
__global__ void detect_dtype(const void* ei, const void* batch){
  if (threadIdx.x != 0 || blockIdx.x != 0) return;
  const int* w = (const int*)ei;
  int all0 = 1;
  for (int i = 0; i < 64; i++){
    long long pos = 2LL*(i*12147 + 7) + 1;   // odd words, < 1.6M
    if (w[pos] != 0){ all0 = 0; break; }
  }
  g_ei64 = all0;
  const int* b = (const int*)batch;
  int all0b = 1;
  for (int i = 0; i < 32; i++){
    int pos = 49001 + 2*i;
    if (b[pos] != 0){ all0b = 0; break; }
  }
  g_b64 = all0b;
}

// ---------------- CSR build -------------------------------------------------
__global__ void deg_zero(){
  int i = blockIdx.x*blockDim.x + threadIdx.x;
  if (i < NN) g_deg[i] = 0;
}
__global__ void deg_hist(const void* __restrict__ ei){
  int e = blockIdx.x*blockDim.x + threadIdx.x;
  if (e >= EE) return;
  int is64 = g_ei64;
  int d = clampi(getIdx(ei, (long long)EE + e, is64), 0, NN-1);
  atomicAdd(&g_deg[d], 1);
}
__global__ void __launch_bounds__(1024) scan_part(){
  int t = threadIdx.x;
  int i = blockIdx.x*1024 + t;
  int v = (i < NN) ? g_deg[i] : 0;
  int lane = t & 31, w = t >> 5;
  int s = v;
  #pragma unroll
  for (int o = 16; o; o >>= 1) s += __shfl_xor_sync(FULLM, s, o);
  __shared__ int ws[32];
  if (lane == 0) ws[w] = s;
  __syncthreads();
  if (w == 0){
    int x = ws[lane];
    #pragma unroll
    for (int o = 16; o; o >>= 1) x += __shfl_xor_sync(FULLM, x, o);
    if (lane == 0) g_part[blockIdx.x] = x;
  }
}
__global__ void __launch_bounds__(64) scan_base(){
  int t = threadIdx.x, lane = t & 31, w = t >> 5;
  int v = (t < SCB) ? g_part[t] : 0;
  int x = v;
  #pragma unroll
  for (int o = 1; o < 32; o <<= 1){
    int y = __shfl_up_sync(FULLM, x, o);
    if (lane >= o) x += y;
  }
  __shared__ int w0;
  if (w == 0 && lane == 31) w0 = x;
  __syncthreads();
  int incl = x + (w ? w0 : 0);
  if (t < SCB) g_part[t] = incl - v;
  if (t == SCB-1) g_off[NN] = incl;
}
__global__ void __launch_bounds__(1024) scan_final(){
  int t = threadIdx.x;
  int i = blockIdx.x*1024 + t;
  int v = (i < NN) ? g_deg[i] : 0;
  int lane = t & 31, w = t >> 5;
  int x = v;
  #pragma unroll
  for (int o = 1; o < 32; o <<= 1){
    int y = __shfl_up_sync(FULLM, x, o);
    if (lane >= o) x += y;
  }
  __shared__ int ws[32];
  if (lane == 31) ws[w] = x;
  __syncthreads();
  if (w == 0){
    int s = ws[lane];
    #pragma unroll
    for (int o = 1; o < 32; o <<= 1){
      int y = __shfl_up_sync(FULLM, s, o);
      if (lane >= o) s += y;
    }
    ws[lane] = s;
  }
  __syncthreads();
  int incl = x + (w ? ws[w-1] : 0);
  int ex = g_part[blockIdx.x] + incl - v;
  if (i < NN){ g_off[i] = ex; g_cur[i] = ex; }
}
__global__ void csr_scatter(const void* __restrict__ ei){
  int e = blockIdx.x*blockDim.x + threadIdx.x;
  if (e >= EE) return;
  int is64 = g_ei64;
  int s = clampi(getIdx(ei, e, is64), 0, NN-1);
  int d = clampi(getIdx(ei, (long long)EE + e, is64), 0, NN-1);
  int p = atomicAdd(&g_cur[d], 1);
  if (p < EE) g_csr[p] = make_int2(s, e);
}

// ---------------- weight prep -----------------------------------------------
__global__ void build_wcat(const float* __restrict__ wq, const float* __restrict__ bq,
                           const float* __restrict__ wk, const float* __restrict__ bk,
                           const float* __restrict__ wv, const float* __restrict__ bv,
                           const float* __restrict__ we, const float* __restrict__ ws,
                           const float* __restrict__ bs, int which){
  int idx = blockIdx.x*blockDim.x + threadIdx.x;
  if (idx < DH*272){
    int j = idx / 272, c = idx % 272;
    float val;
    if      (c < 64)  val = wq[j*64 + c];
    else if (c < 128) val = wk[j*64 + (c-64)];
    else if (c < 192) val = wv[j*64 + (c-128)];
    else if (c < 256) val = ws[j*64 + (c-192)];
    else { int d = c-256; float s = 0.f;
           for (int cc = 0; cc < 64; cc++) s += wq[j*64+cc]*we[d*64+cc];
           val = s; }
    g_Wcat[which][j*272 + c] = val;
  }
  if (idx < 272){
    int c = idx; float val;
    if      (c < 64)  val = bq[c];
    else if (c < 128) val = bk[c-64];
    else if (c < 192) val = bv[c-128];
    else if (c < 256) val = bs[c-192];
    else { int d = c-256; float s = 0.f;
           for (int cc = 0; cc < 64; cc++) s += bq[cc]*we[d*64+cc];
           val = s; }
    g_Bcat[which][c] = val;
  }
}

// ---------------- node GEMM (FFMA2): [NPB,64] x [64,272] --------------------
__global__ void __launch_bounds__(256) node_linear(const float* __restrict__ xin,
                                                   int useH, int which){
  __shared__ __align__(16) float xs[NPB*65];
  __shared__ __align__(16) float sW[64*64];
  const float* src = useH ? g_h : xin;
  const float* Wc = g_Wcat[which];
  const float* Bc = g_Bcat[which];
  int t = threadIdx.x;
  int nbase = blockIdx.x * NPB;

  for (int idx = t; idx < NPB*64; idx += 256){
    int n = idx >> 6, kk = idx & 63;
    int gn = nbase + n;
    xs[n*65 + kk] = (gn < NN) ? src[gn*64 + kk] : 0.f;
  }
  __syncthreads();

  int cg = t & 15, ng = t >> 4;
  for (int ct = 0; ct < 5; ct++){
    int col0 = ct*64;
    int tw = (ct == 4) ? 16 : 64;
    for (int idx = t; idx < 64*tw; idx += 256){
      int kk = idx / tw, c = idx - kk*tw;
      sW[kk*64 + c] = Wc[kk*272 + col0 + c];
    }
    __syncthreads();
    if (ct < 4 || cg < 4){
      unsigned long long acclo[7], acchi[7];
      #pragma unroll
      for (int i = 0; i < 7; i++){ acclo[i] = 0ull; acchi[i] = 0ull; }
      #pragma unroll 8
      for (int kk = 0; kk < 64; kk++){
        float4 w4 = *(const float4*)&sW[kk*64 + cg*4];
        unsigned long long wlo = pk(w4.x, w4.y);
        unsigned long long whi = pk(w4.z, w4.w);
        #pragma unroll
        for (int i = 0; i < 7; i++){
          float xv = xs[(ng + i*16)*65 + kk];
          unsigned long long xx = pk(xv, xv);
          ffma2(acclo[i], wlo, xx);
          ffma2(acchi[i], whi, xx);
        }
      }
      float* outp = (ct==0) ? g_q : (ct==1) ? g_k : (ct==2) ? g_v : (ct==3) ? g_agg : g_qwe;
      int ow = (ct == 4) ? 16 : 64;
      float b0 = Bc[col0 + cg*4 + 0];
      float b1 = Bc[col0 + cg*4 + 1];
      float b2 = Bc[col0 + cg*4 + 2];
      float b3 = Bc[col0 + cg*4 + 3];
      #pragma unroll
      for (int i = 0; i < 7; i++){
        int gn = nbase + ng + i*16;
        if (gn < NN){
          float l0, l1, h0, h1;
          upk(acclo[i], l0, l1); upk(acchi[i], h0, h1);
          float4 r; r.x = l0 + b0; r.y = l1 + b1; r.z = h0 + b2; r.w = h1 + b3;
          *(float4*)&outp[gn*ow + cg*4] = r;
        }
      }
    }
    __syncthreads();
  }
}

// ---------------- fused attention: warp/node, two-phase chunks --------------
__global__ void __launch_bounds__(256) fused_attn(const float* __restrict__ ea,
                                                  const float* __restrict__ we,
                                                  float* __restrict__ emb_out,
                                                  int finalLayer){
  __shared__ __align__(16) float sWe[DE*DH];
  __shared__ float sS[8][32];
  int t = threadIdx.x;
  for (int i = t; i < DE*DH; i += 256) sWe[i] = we[i];
  __syncthreads();

  int lane = t & 31, w = t >> 5;
  int n = blockIdx.x*8 + w;
  if (n >= NN) return;

  int hl = lane & 15;        // lane within half-warp
  int half = lane >> 4;      // which edge of a pair

  float4 q4 = *(const float4*)&g_q[n*64 + hl*4];
  float4 qe4 = make_float4(0.f,0.f,0.f,0.f);
  if (hl < 4) qe4 = *(const float4*)&g_qwe[n*16 + hl*4];

  int s0 = g_off[n], s1 = g_off[n+1];

  float m = -1e30f, den = 0.f;
  float2 accv = make_float2(0.f, 0.f);   // lane covers v channels lane*2, lane*2+1
  float2 acce = make_float2(0.f, 0.f);   // lanes 0..7 cover ea dims lane*2, lane*2+1

  for (int base = s0; base < s1; base += 32){
    int cnt = min(32, s1 - base);
    int2 se = (lane < cnt) ? g_csr[base + lane] : make_int2(0, 0);
    int npair = (cnt + 1) >> 1;

    // ---- phase A: independent score computation (pairs via half-warps) ----
    for (int j = 0; j < npair; j++){
      int sl = 2*j + half;
      int srcn = __shfl_sync(FULLM, se.x, sl & 31);
      int eid  = __shfl_sync(FULLM, se.y, sl & 31);
      float4 k4 = *(const float4*)&g_k[srcn*64 + hl*4];
      float part = q4.x*k4.x + q4.y*k4.y + q4.z*k4.z + q4.w*k4.w;
      if (hl < 4){
        float4 ea4 = *(const float4*)&ea[(long long)eid*16 + hl*4];
        part += qe4.x*ea4.x + qe4.y*ea4.y + qe4.z*ea4.z + qe4.w*ea4.w;
      }
      part += __shfl_xor_sync(FULLM, part, 8);
      part += __shfl_xor_sync(FULLM, part, 4);
      part += __shfl_xor_sync(FULLM, part, 2);
      part += __shfl_xor_sync(FULLM, part, 1);
      if (hl == 0) sS[w][sl] = part * 0.125f;
    }
    __syncwarp();
    float sc = (lane < cnt) ? sS[w][lane] : -1e30f;
    __syncwarp();

    // ---- chunk softmax: vectorized max/exp/den ----
    float cm = sc;
    #pragma unroll
    for (int o = 16; o; o >>= 1) cm = fmaxf(cm, __shfl_xor_sync(FULLM, cm, o));
    float newm = fmaxf(m, cm);
    float scale = __expf(m - newm);
    float p = (lane < cnt) ? __expf(sc - newm) : 0.f;
    float cden = p;
    #pragma unroll
    for (int o = 16; o; o >>= 1) cden += __shfl_xor_sync(FULLM, cden, o);
    den = den*scale + cden;
    accv.x *= scale; accv.y *= scale;
    acce.x *= scale; acce.y *= scale;
    m = newm;

    // ---- phase B: weighted aggregation (1 SHFL + 1-2 LDG per edge) ----
    for (int j = 0; j < cnt; j++){
      float pj  = __shfl_sync(FULLM, p, j);
      int srcn  = __shfl_sync(FULLM, se.x, j);
      int eid   = __shfl_sync(FULLM, se.y, j);
      float2 v2 = *(const float2*)&g_v[srcn*64 + lane*2];
      accv.x = fmaf(pj, v2.x, accv.x);
      accv.y = fmaf(pj, v2.y, accv.y);
      if (lane < 8){
        float2 e2 = *(const float2*)&ea[(long long)eid*16 + lane*2];
        acce.x = fmaf(pj, e2.x, acce.x);
        acce.y = fmaf(pj, e2.y, acce.y);
      }
    }
  }

  float invden = (den > 0.f) ? (1.f / den) : 0.f;
  accv.x *= invden; accv.y *= invden;
  acce.x *= invden; acce.y *= invden;

  // edge-attr contribution through we: out += acce(16) @ we(16x64)
  float2 r = make_float2(0.f, 0.f);
  #pragma unroll
  for (int d = 0; d < 16; d++){
    float ev = __shfl_sync(FULLM, (d & 1) ? acce.y : acce.x, d >> 1);
    r.x = fmaf(ev, sWe[d*64 + lane*2],     r.x);
    r.y = fmaf(ev, sWe[d*64 + lane*2 + 1], r.y);
  }

  float2 sk = *(const float2*)&g_agg[n*64 + lane*2];
  float o0 = leaky(sk.x + accv.x + r.x);
  float o1 = leaky(sk.y + accv.y + r.y);
  float* dst = finalLayer ? emb_out : g_h;
  *(float2*)&dst[n*64 + lane*2] = make_float2(o0, o1);
}

// ---------------- pooling (batch is sorted) ---------------------------------
__device__ __forceinline__ int lbidx(const void* b, int val, int is64){
  int lo = 0, hi = NN;
  while (lo < hi){
    int mid = (lo + hi) >> 1;
    int v = is64 ? (int)((const long long*)b)[mid] : ((const int*)b)[mid];
    if (v < val) lo = mid + 1; else hi = mid;
  }
  return lo;
}
__global__ void __launch_bounds__(256) pool_kernel(const void* __restrict__ batch,
                                                   const float* __restrict__ embs){
  __shared__ float sp[4][64];
  int g = blockIdx.x;
  int t = threadIdx.x;
  int ch = t & 63, r = t >> 6;
  int is64 = g_b64;
  int s = lbidx(batch, g, is64);
  int e = lbidx(batch, g + 1, is64);
  float sum = 0.f;
  for (int n = s + r; n < e; n += 4) sum += embs[n*64 + ch];
  sp[r][ch] = sum;
  __syncthreads();
  if (r == 0)
    g_pooled[g*64 + ch] = sp[0][ch] + sp[1][ch] + sp[2][ch] + sp[3][ch];
}

// ---------------- head ------------------------------------------------------
__global__ void __launch_bounds__(256) fc_kernel(const float* __restrict__ wfc1,
                                                 const float* __restrict__ bfc1,
                                                 const float* __restrict__ wfc2,
                                                 const float* __restrict__ bfc2,
                                                 float* __restrict__ out){
  __shared__ __align__(16) float sW1[64*64];
  __shared__ float sW2[64];
  __shared__ float sB1[64];
  int t = threadIdx.x;
  for (int i = t; i < 4096; i += 256) sW1[i] = wfc1[i];
  if (t < 64){ sW2[t] = wfc2[t]; sB1[t] = bfc1[t]; }
  __syncthreads();
  int lane = t & 31, w = t >> 5;
  int g = blockIdx.x*8 + w;
  if (g >= GG) return;
  float p0 = g_pooled[g*64 + lane], p1 = g_pooled[g*64 + 32 + lane];
  float ss = p0*p0 + p1*p1;
  #pragma unroll
  for (int o = 16; o; o >>= 1) ss += __shfl_xor_sync(FULLM, ss, o);
  float inv = 1.f / fmaxf(sqrtf(ss), 1e-12f);
  float h0 = p0*inv, h1 = p1*inv;
  float acc0 = sB1[lane], acc1 = sB1[32 + lane];
  #pragma unroll
  for (int j = 0; j < 64; j++){
    float hj = (j < 32) ? __shfl_sync(FULLM, h0, j)
                        : __shfl_sync(FULLM, h1, j-32);
    acc0 += hj * sW1[j*64 + lane];
    acc1 += hj * sW1[j*64 + 32 + lane];
  }
  acc0 = leaky(acc0); acc1 = leaky(acc1);
  float r = acc0*sW2[lane] + acc1*sW2[32 + lane];
  #pragma unroll
  for (int o = 16; o; o >>= 1) r += __shfl_xor_sync(FULLM, r, o);
  if (lane == 0) out[g] = r + bfc2[0];
}

// ---------------- launch ----------------------------------------------------
extern "C" void kernel_launch(void* const* d_in, const int* in_sizes, int n_in,
                              void* d_out, int out_size){
  int ix = -1, ie = -1, iea = -1, ib = -1;
  for (int i = 0; i < n_in; i++){
    if      (in_sizes[i] == NN*DH)   ix  = i;
    else if (in_sizes[i] == 2*EE)    ie  = i;
    else if (in_sizes[i] == EE*DE)   iea = i;
    else if (in_sizes[i] == NN)      ib  = i;
  }
  if (ix < 0) ix = 0; if (ie < 0) ie = 1; if (iea < 0) iea = 2; if (ib < 0) ib = 3;

  const float* x     = (const float*)d_in[ix];
  const void*  ei    = d_in[ie];
  const float* ea    = (const float*)d_in[iea];
  const void*  batch = d_in[ib];

  const float* wp[22]; int nw = 0;
  for (int i = 0; i < n_in && nw < 22; i++){
    if (i == ix || i == ie || i == iea || i == ib) continue;
    wp[nw++] = (const float*)d_in[i];
  }
  const float *wq1=wp[0],  *bq1=wp[1],  *wk1=wp[2],  *bk1=wp[3];
  const float *wv1=wp[4],  *bv1=wp[5],  *we1=wp[6],  *ws1=wp[7],  *bs1=wp[8];
  const float *wq2=wp[9],  *bq2=wp[10], *wk2=wp[11], *bk2=wp[12];
  const float *wv2=wp[13], *bv2=wp[14], *we2=wp[15], *ws2=wp[16], *bs2=wp[17];
  const float *wfc1=wp[18], *bfc1=wp[19], *wfc2=wp[20], *bfc2=wp[21];

  float* out  = (float*)d_out;
  float* embs = out + GG;   // tuple order: (out[512,1], atom_embs[50000,64])

  const int GRID_NL = (NN + NPB - 1) / NPB;   // 447
  const int GRID_E  = EE / 256;               // 3125 exact
  const int GRID_N  = (NN + 255) / 256;       // 196
  const int GRID_FA = (NN + 7) / 8;           // 6250

  // Launch order puts node_linear at index 3 (the launch ncu captures).
  build_wcat<<<68, 256>>>(wq1, bq1, wk1, bk1, wv1, bv1, we1, ws1, bs1, 0);  // 0
  detect_dtype<<<1, 32>>>(ei, batch);                                      // 1
  deg_zero<<<GRID_N, 256>>>();                                             // 2
  node_linear<<<GRID_NL, 256>>>(x, 0, 0);                                  // 3 (profiled)
  deg_hist<<<GRID_E, 256>>>(ei);                                           // 4
  scan_part<<<SCB, 1024>>>();                                              // 5
  scan_base<<<1, 64>>>();                                                  // 6
  scan_final<<<SCB, 1024>>>();                                             // 7
  csr_scatter<<<GRID_E, 256>>>(ei);                                        // 8
  build_wcat<<<68, 256>>>(wq2, bq2, wk2, bk2, wv2, bv2, we2, ws2, bs2, 1); // 9
  fused_attn<<<GRID_FA, 256>>>(ea, we1, nullptr, 0);                       // 10
  node_linear<<<GRID_NL, 256>>>(x, 1, 1);                                  // 11
  fused_attn<<<GRID_FA, 256>>>(ea, we2, embs, 1);                          // 12
  pool_kernel<<<GG, 256>>>(batch, embs);                                   // 13
  fc_kernel<<<(GG + 7) / 8, 256>>>(wfc1, bfc1, wfc2, bfc2, out);           // 14
}